// round 16
// baseline (speedup 1.0000x reference)
#include <cuda_runtime.h>
#include <cuda_fp16.h>
#include <cstdint>

#define N_NODES 50000
#define N_EDGES 800000
#define E_TOT   (N_EDGES + N_NODES)
#define IN_DIM  256
#define OUT_DIM 256   // N_HEADS * HEAD_DIM
#define NEG_SLOPE 0.2f
#define NBLK_SCAN ((N_NODES + 255) / 256)   // 196

// ---------------- scratch (static device globals; no runtime allocation) ---
__device__ __align__(16) __half g_xph[(size_t)N_NODES * OUT_DIM]; // projected features, fp16 [N,256]
__device__ __align__(16) float g_asrc[N_NODES * 4];               // per-node src logits [N,4]
__device__ __align__(16) float g_adst[N_NODES * 4];               // per-node dst logits [N,4]
__device__ int g_csr_src[E_TOT];                                  // src node id, CSR order
__device__ int g_deg[N_NODES];                                    // in-degree histogram
__device__ int g_off[N_NODES];                                    // CSR row start (block-LOCAL exclusive)
__device__ int g_cur[N_NODES];                                    // scatter cursor (block-LOCAL)
__device__ int g_bsum[NBLK_SCAN];                                 // per-block degree sums
__device__ int g_boff[NBLK_SCAN];                                 // scanned block offsets
__device__ int g_scan_ctr;                                        // last-block ticket
__device__ int g_is64;                                            // edge_index dtype flag

// ---------------- helpers --------------------------------------------------
__device__ __forceinline__ uint32_t f2tf32(float f) {
    uint32_t r;
    asm("cvt.rna.tf32.f32 %0, %1;" : "=r"(r) : "f"(f));
    return r;
}

__device__ __forceinline__ void load_edge(const void* ei, int i, int& s, int& d) {
    if (g_is64) {
        const long long* p = (const long long*)ei;
        s = (int)p[i];
        d = (int)p[N_EDGES + i];
    } else {
        const int* p = (const int*)ei;
        s = p[i];
        d = p[N_EDGES + i];
    }
}

// ---------------- K0: zero degrees + ticket + dtype detect (side stream) ---
__global__ void zero_deg_kernel(const int* __restrict__ ei32) {
    __shared__ int s_any[128];
    int i = blockIdx.x * blockDim.x + threadIdx.x;
    if (i < N_NODES) g_deg[i] = 0;
    if (blockIdx.x == 0) {
        int t = threadIdx.x;
        if (t == 0) g_scan_ctr = 0;
        if (t < 128) s_any[t] = ei32[2 * t + 1];   // parallel probe of odd words
        __syncthreads();
        if (t < 64) s_any[t] |= s_any[t + 64];
        __syncthreads();
        if (t < 32) {
            int v = s_any[t] | s_any[t + 32];
#pragma unroll
            for (int off = 16; off > 0; off >>= 1)
                v |= __shfl_down_sync(0xffffffffu, v, off);
            if (t == 0) g_is64 = (v == 0) ? 1 : 0;
        }
    }
}

// ---------------- K1: GEMM xp = x @ W (tf32 mma, cp.async 3-stage, ---------
//                      fused atomic-free logit epilogue, 2 CTAs/SM)
#define GBM 128
#define GBN 128
#define GBK 32
#define NK_IT (IN_DIM / GBK)      // 8
#define A_LD 36
#define B_LD 136
#define A_STG_B (GBM * A_LD * 4)
#define B_STG_B (GBK * B_LD * 4)
#define B_BASE_B (3 * A_STG_B)
#define GEMM_SMEM (3 * (A_STG_B + B_STG_B))  // 107520

__global__ __launch_bounds__(256, 2) void gemm_tf32_kernel(
    const float* __restrict__ X, const float* __restrict__ Wm,
    const float* __restrict__ att_src, const float* __restrict__ att_dst)
{
    extern __shared__ char smem_raw[];
    float* Asf = reinterpret_cast<float*>(smem_raw);
    float* Bsf = reinterpret_cast<float*>(smem_raw + B_BASE_B);
    const uint32_t sbase = (uint32_t)__cvta_generic_to_shared(smem_raw);

    const int tid  = threadIdx.x;
    const int wid  = tid >> 5;
    const int lane = tid & 31;
    const int m0 = blockIdx.x * GBM;
    const int n0 = blockIdx.y * GBN;
    const int wm = (wid & 1) * 64;
    const int wn = (wid >> 1) * 32;
    const int gID = lane >> 2;
    const int tig = lane & 3;

#define ISSUE_STAGE(K0, STG) do {                                              \
        _Pragma("unroll")                                                      \
        for (int l = 0; l < 4; l++) {                                          \
            int idx = tid + l * 256;                                           \
            int row = idx >> 3, c4 = idx & 7;                                  \
            int gm = m0 + row;                                                 \
            int sz = (gm < N_NODES) ? 16 : 0;                                  \
            if (gm >= N_NODES) gm = N_NODES - 1;                               \
            uint32_t dst = sbase + (STG) * A_STG_B + row * (A_LD * 4) + c4 * 16;\
            const char* src = (const char*)X + (size_t)gm * (IN_DIM * 4)       \
                              + (K0) * 4 + c4 * 16;                            \
            asm volatile("cp.async.cg.shared.global [%0], [%1], 16, %2;"       \
                         :: "r"(dst), "l"(src), "r"(sz));                      \
        }                                                                      \
        _Pragma("unroll")                                                      \
        for (int l = 0; l < 4; l++) {                                          \
            int idx = tid + l * 256;                                           \
            int kr = idx >> 5, c4 = idx & 31;                                  \
            uint32_t dst = sbase + B_BASE_B + (STG) * B_STG_B                  \
                           + kr * (B_LD * 4) + c4 * 16;                        \
            const char* src = (const char*)Wm                                  \
                + ((size_t)((K0) + kr) * OUT_DIM + n0) * 4 + c4 * 16;          \
            asm volatile("cp.async.cg.shared.global [%0], [%1], 16;"           \
                         :: "r"(dst), "l"(src));                               \
        }                                                                      \
        asm volatile("cp.async.commit_group;" ::: "memory");                   \
    } while (0)

    float c[4][4][4];
#pragma unroll
    for (int i = 0; i < 4; i++)
#pragma unroll
        for (int j = 0; j < 4; j++)
#pragma unroll
            for (int r = 0; r < 4; r++) c[i][j][r] = 0.f;

    ISSUE_STAGE(0, 0);
    ISSUE_STAGE(GBK, 1);

    for (int it = 0; it < NK_IT; it++) {
        if (it == NK_IT - 1) asm volatile("cp.async.wait_group 0;" ::: "memory");
        else                 asm volatile("cp.async.wait_group 1;" ::: "memory");
        __syncthreads();

        const int stg = it % 3;
        const float* Af = Asf + stg * (GBM * A_LD);
        const float* Bf = Bsf + stg * (GBK * B_LD);

#pragma unroll
        for (int ks = 0; ks < 4; ks++) {
            const int kb = ks * 8;
            uint32_t a[4][4], b[4][2];
#pragma unroll
            for (int mt = 0; mt < 4; mt++) {
                int rb = wm + mt * 16;
                a[mt][0] = f2tf32(Af[(rb + gID    ) * A_LD + kb + tig    ]);
                a[mt][1] = f2tf32(Af[(rb + gID + 8) * A_LD + kb + tig    ]);
                a[mt][2] = f2tf32(Af[(rb + gID    ) * A_LD + kb + tig + 4]);
                a[mt][3] = f2tf32(Af[(rb + gID + 8) * A_LD + kb + tig + 4]);
            }
#pragma unroll
            for (int nt = 0; nt < 4; nt++) {
                int col = wn + nt * 8 + gID;
                b[nt][0] = f2tf32(Bf[(kb + tig    ) * B_LD + col]);
                b[nt][1] = f2tf32(Bf[(kb + tig + 4) * B_LD + col]);
            }
#pragma unroll
            for (int mt = 0; mt < 4; mt++)
#pragma unroll
                for (int nt = 0; nt < 4; nt++) {
                    asm volatile(
                        "mma.sync.aligned.m16n8k8.row.col.f32.tf32.tf32.f32 "
                        "{%0,%1,%2,%3}, {%4,%5,%6,%7}, {%8,%9}, {%0,%1,%2,%3};"
                        : "+f"(c[mt][nt][0]), "+f"(c[mt][nt][1]),
                          "+f"(c[mt][nt][2]), "+f"(c[mt][nt][3])
                        : "r"(a[mt][0]), "r"(a[mt][1]), "r"(a[mt][2]), "r"(a[mt][3]),
                          "r"(b[nt][0]), "r"(b[nt][1]));
                }
        }

        if (it + 2 < NK_IT) {
            ISSUE_STAGE((it + 2) * GBK, (it + 2) % 3);
        }
    }
#undef ISSUE_STAGE

    // ---- epilogue 1: fp16 xp stores ----
#pragma unroll
    for (int mt = 0; mt < 4; mt++) {
        int r0 = m0 + wm + mt * 16 + gID;
#pragma unroll
        for (int nt = 0; nt < 4; nt++) {
            int col = n0 + wn + nt * 8 + 2 * tig;
            if (r0 < N_NODES) {
                __half2 v01 = __floats2half2_rn(c[mt][nt][0], c[mt][nt][1]);
                *reinterpret_cast<__half2*>(g_xph + (size_t)r0 * OUT_DIM + col) = v01;
            }
            if (r0 + 8 < N_NODES) {
                __half2 v23 = __floats2half2_rn(c[mt][nt][2], c[mt][nt][3]);
                *reinterpret_cast<__half2*>(g_xph + (size_t)(r0 + 8) * OUT_DIM + col) = v23;
            }
        }
    }

    // ---- epilogue 2: attention logits, atomic-free -------------------------
    float psrc0[4], psrc1[4], pdst0[4], pdst1[4];
#pragma unroll
    for (int mt = 0; mt < 4; mt++) {
        psrc0[mt] = psrc1[mt] = pdst0[mt] = pdst1[mt] = 0.f;
#pragma unroll
        for (int nt = 0; nt < 4; nt++) {
            int col = n0 + wn + nt * 8 + 2 * tig;
            float as0 = att_src[col], as1 = att_src[col + 1];
            float ad0 = att_dst[col], ad1 = att_dst[col + 1];
            psrc0[mt] += c[mt][nt][0] * as0 + c[mt][nt][1] * as1;
            psrc1[mt] += c[mt][nt][2] * as0 + c[mt][nt][3] * as1;
            pdst0[mt] += c[mt][nt][0] * ad0 + c[mt][nt][1] * ad1;
            pdst1[mt] += c[mt][nt][2] * ad0 + c[mt][nt][3] * ad1;
        }
    }
#pragma unroll
    for (int off = 1; off <= 2; off <<= 1) {
#pragma unroll
        for (int mt = 0; mt < 4; mt++) {
            psrc0[mt] += __shfl_xor_sync(0xffffffffu, psrc0[mt], off);
            psrc1[mt] += __shfl_xor_sync(0xffffffffu, psrc1[mt], off);
            pdst0[mt] += __shfl_xor_sync(0xffffffffu, pdst0[mt], off);
            pdst1[mt] += __shfl_xor_sync(0xffffffffu, pdst1[mt], off);
        }
    }
    float* red = reinterpret_cast<float*>(smem_raw);   // reuse pipeline smem
    __syncthreads();
    if (tig == 0) {
#pragma unroll
        for (int mt = 0; mt < 4; mt++) {
            int base = wid * 128 + mt * 32 + gID;
            red[base +  0] = psrc0[mt];
            red[base +  8] = psrc1[mt];
            red[base + 16] = pdst0[mt];
            red[base + 24] = pdst1[mt];
        }
    }
    __syncthreads();
    if ((((wid >> 1) & 1) == 0) && tig == 0) {
        int pw = wid + 2;                       // partner warp (wn + 32)
        int h = (n0 + wn) >> 6;                 // global head 0..3
#pragma unroll
        for (int mt = 0; mt < 4; mt++) {
            int pb = pw * 128 + mt * 32 + gID;
            float s0 = psrc0[mt] + red[pb +  0];
            float s1 = psrc1[mt] + red[pb +  8];
            float d0 = pdst0[mt] + red[pb + 16];
            float d1 = pdst1[mt] + red[pb + 24];
            int r0 = m0 + wm + mt * 16 + gID;
            if (r0 < N_NODES) {
                g_asrc[r0 * 4 + h] = s0;
                g_adst[r0 * 4 + h] = d0;
            }
            if (r0 + 8 < N_NODES) {
                g_asrc[(r0 + 8) * 4 + h] = s1;
                g_adst[(r0 + 8) * 4 + h] = d1;
            }
        }
    }
}

// ---------------- K3a: in-degree histogram ---------------------------------
__global__ __launch_bounds__(256) void hist_kernel(const void* __restrict__ ei)
{
    int i = blockIdx.x * blockDim.x + threadIdx.x;
    if (i >= E_TOT) return;
    int s, d;
    if (i < N_EDGES) load_edge(ei, i, s, d);
    else             d = i - N_EDGES;
    atomicAdd(&g_deg[d], 1);
}

// ---------------- K3b: fused exclusive scan (last-block-done pattern) ------
__global__ __launch_bounds__(256) void scan_fused_kernel()
{
    __shared__ int sm[256];
    __shared__ bool isLast;
    int tid = threadIdx.x;
    int i = blockIdx.x * 256 + tid;
    int v = (i < N_NODES) ? g_deg[i] : 0;
    sm[tid] = v;
    __syncthreads();
#pragma unroll
    for (int off = 1; off < 256; off <<= 1) {
        int t = (tid >= off) ? sm[tid - off] : 0;
        __syncthreads();
        sm[tid] += t;
        __syncthreads();
    }
    int incl = sm[tid];
    if (i < N_NODES) {
        int excl = incl - v;
        g_off[i] = excl;
        g_cur[i] = excl;
    }
    if (tid == 255) g_bsum[blockIdx.x] = incl;

    __threadfence();
    if (tid == 0) {
        int ticket = atomicAdd(&g_scan_ctr, 1);
        isLast = (ticket == gridDim.x - 1);
    }
    __syncthreads();
    if (isLast) {
        int bv = (tid < NBLK_SCAN) ? g_bsum[tid] : 0;
        sm[tid] = bv;
        __syncthreads();
#pragma unroll
        for (int off = 1; off < 256; off <<= 1) {
            int t = (tid >= off) ? sm[tid - off] : 0;
            __syncthreads();
            sm[tid] += t;
            __syncthreads();
        }
        if (tid < NBLK_SCAN) g_boff[tid] = sm[tid] - bv;
    }
}

// ---------------- K3c: scatter edges into CSR order (index only) -----------
__global__ __launch_bounds__(256) void scatter_kernel(const void* __restrict__ ei)
{
    int i = blockIdx.x * blockDim.x + threadIdx.x;
    if (i >= E_TOT) return;
    int s, d;
    if (i < N_EDGES) load_edge(ei, i, s, d);
    else             s = d = i - N_EDGES;   // self-loop

    int pos = atomicAdd(&g_cur[d], 1) + g_boff[d >> 8];
    g_csr_src[pos] = s;
}

// ---------------- K4: CSR aggregate, 1 warp/node, depth-1 gather pipeline --
__global__ __launch_bounds__(256) void aggregate_csr_kernel(float* __restrict__ out)
{
    int d = (blockIdx.x * blockDim.x + threadIdx.x) >> 5;
    if (d >= N_NODES) return;
    int lane = threadIdx.x & 31;
    int h = lane >> 3;
    int boff = g_boff[d >> 8];
    int beg = g_off[d] + boff;
    int end = g_cur[d] + boff;
    float adh = __ldg(g_adst + d * 4 + h);   // invariant over the row

    float a0 = 0.f, a1 = 0.f, a2 = 0.f, a3 = 0.f;
    float a4 = 0.f, a5 = 0.f, a6 = 0.f, a7 = 0.f;
    float denom = 0.f;

#define ACC_EDGE(U, EW) do {                                                   \
        const __half2* hp = reinterpret_cast<const __half2*>(&(U));            \
        float2 f0 = __half22float2(hp[0]);                                     \
        float2 f1 = __half22float2(hp[1]);                                     \
        float2 f2 = __half22float2(hp[2]);                                     \
        float2 f3 = __half22float2(hp[3]);                                     \
        a0 += (EW) * f0.x; a1 += (EW) * f0.y;                                  \
        a2 += (EW) * f1.x; a3 += (EW) * f1.y;                                  \
        a4 += (EW) * f2.x; a5 += (EW) * f2.y;                                  \
        a6 += (EW) * f3.x; a7 += (EW) * f3.y;                                  \
    } while (0)

    if (beg < end) {
        // prologue: edge 0 in flight
        int   s = __ldg(g_csr_src + beg);
        float e = __ldg(g_asrc + s * 4 + h) + adh;
        uint4 u = __ldg(reinterpret_cast<const uint4*>(
            g_xph + (size_t)s * OUT_DIM + lane * 8));

        for (int j = beg + 1; j < end; j++) {
            // issue next edge's loads before consuming current
            int   s2 = __ldg(g_csr_src + j);
            float e2 = __ldg(g_asrc + s2 * 4 + h) + adh;
            uint4 u2 = __ldg(reinterpret_cast<const uint4*>(
                g_xph + (size_t)s2 * OUT_DIM + lane * 8));

            float el = (e > 0.f) ? e : NEG_SLOPE * e;
            float ee = __expf(el);
            denom += ee;
            ACC_EDGE(u, ee);

            e = e2; u = u2;
        }
        float el = (e > 0.f) ? e : NEG_SLOPE * e;
        float ee = __expf(el);
        denom += ee;
        ACC_EDGE(u, ee);
    }
#undef ACC_EDGE

    float inv = 1.f / denom;
    float4 o0 = make_float4(fmaxf(a0 * inv, 0.f), fmaxf(a1 * inv, 0.f),
                            fmaxf(a2 * inv, 0.f), fmaxf(a3 * inv, 0.f));
    float4 o1 = make_float4(fmaxf(a4 * inv, 0.f), fmaxf(a5 * inv, 0.f),
                            fmaxf(a6 * inv, 0.f), fmaxf(a7 * inv, 0.f));
    float4* op = reinterpret_cast<float4*>(out + (size_t)d * OUT_DIM + lane * 8);
    __stcs(op, o0);
    __stcs(op + 1, o1);
}

// ---------------- launch ----------------------------------------------------
extern "C" void kernel_launch(void* const* d_in, const int* in_sizes, int n_in,
                              void* d_out, int out_size)
{
    const float* x       = (const float*)d_in[0];
    const void*  ei      = d_in[1];
    const float* Wm      = (const float*)d_in[2];
    const float* att_src = (const float*)d_in[3];
    const float* att_dst = (const float*)d_in[4];
    float*       out     = (float*)d_out;

    static cudaStream_t s1 = nullptr;
    static cudaEvent_t evFork = nullptr, evJoin = nullptr;
    if (!s1) {
        cudaStreamCreateWithFlags(&s1, cudaStreamNonBlocking);
        cudaEventCreateWithFlags(&evFork, cudaEventDisableTiming);
        cudaEventCreateWithFlags(&evJoin, cudaEventDisableTiming);
        cudaFuncSetAttribute(gemm_tf32_kernel,
                             cudaFuncAttributeMaxDynamicSharedMemorySize, GEMM_SMEM);
    }

    cudaEventRecord(evFork, 0);
    cudaStreamWaitEvent(s1, evFork, 0);

    // branch B (side stream): deg-zero+detect -> hist -> scan -> scatter
    zero_deg_kernel<<<NBLK_SCAN, 256, 0, s1>>>((const int*)ei);
    hist_kernel<<<(E_TOT + 255) / 256, 256, 0, s1>>>(ei);
    scan_fused_kernel<<<NBLK_SCAN, 256, 0, s1>>>();
    scatter_kernel<<<(E_TOT + 255) / 256, 256, 0, s1>>>(ei);
    cudaEventRecord(evJoin, s1);

    // branch A (main stream): GEMM + atomic-free logit epilogue
    dim3 ggrid((N_NODES + GBM - 1) / GBM, OUT_DIM / GBN);
    gemm_tf32_kernel<<<ggrid, 256, GEMM_SMEM>>>(x, Wm, att_src, att_dst);

    // join: aggregate needs logits+xp (A) and CSR (B)
    cudaStreamWaitEvent(0, evJoin, 0);
    aggregate_csr_kernel<<<((size_t)N_NODES * 32 + 255) / 256, 256>>>(out);
}

// round 17
// speedup vs baseline: 1.4988x; 1.4988x over previous
#include <cuda_runtime.h>
#include <cuda_fp16.h>
#include <cstdint>

#define N_NODES 50000
#define N_EDGES 800000
#define E_TOT   (N_EDGES + N_NODES)
#define IN_DIM  256
#define OUT_DIM 256   // N_HEADS * HEAD_DIM
#define NEG_SLOPE 0.2f
#define NBLK_SCAN ((N_NODES + 255) / 256)   // 196

// ---------------- scratch (static device globals; no runtime allocation) ---
__device__ __align__(16) __half g_xph[(size_t)N_NODES * OUT_DIM]; // projected features, fp16 [N,256]
__device__ __align__(16) float g_asrc[N_NODES * 4];               // per-node src logits [N,4]
__device__ __align__(16) float g_adst[N_NODES * 4];               // per-node dst logits [N,4]
__device__ int g_csr_src[E_TOT];                                  // src node id, CSR order
__device__ int g_deg[N_NODES];                                    // in-degree histogram
__device__ int g_off[N_NODES];                                    // CSR row start (block-LOCAL exclusive)
__device__ int g_cur[N_NODES];                                    // scatter cursor (block-LOCAL)
__device__ int g_bsum[NBLK_SCAN];                                 // per-block degree sums
__device__ int g_boff[NBLK_SCAN];                                 // scanned block offsets
__device__ int g_scan_ctr;                                        // last-block ticket
__device__ int g_is64;                                            // edge_index dtype flag

// ---------------- helpers --------------------------------------------------
__device__ __forceinline__ uint32_t f2tf32(float f) {
    uint32_t r;
    asm("cvt.rna.tf32.f32 %0, %1;" : "=r"(r) : "f"(f));
    return r;
}

__device__ __forceinline__ void load_edge(const void* ei, int i, int& s, int& d) {
    if (g_is64) {
        const long long* p = (const long long*)ei;
        s = (int)p[i];
        d = (int)p[N_EDGES + i];
    } else {
        const int* p = (const int*)ei;
        s = p[i];
        d = p[N_EDGES + i];
    }
}

// ---------------- K0: zero degrees + ticket + dtype detect (side stream) ---
__global__ void zero_deg_kernel(const int* __restrict__ ei32) {
    __shared__ int s_any[128];
    int i = blockIdx.x * blockDim.x + threadIdx.x;
    if (i < N_NODES) g_deg[i] = 0;
    if (blockIdx.x == 0) {
        int t = threadIdx.x;
        if (t == 0) g_scan_ctr = 0;
        if (t < 128) s_any[t] = ei32[2 * t + 1];   // parallel probe of odd words
        __syncthreads();
        if (t < 64) s_any[t] |= s_any[t + 64];
        __syncthreads();
        if (t < 32) {
            int v = s_any[t] | s_any[t + 32];
#pragma unroll
            for (int off = 16; off > 0; off >>= 1)
                v |= __shfl_down_sync(0xffffffffu, v, off);
            if (t == 0) g_is64 = (v == 0) ? 1 : 0;
        }
    }
}

// ---------------- K1: GEMM xp = x @ W (tf32 mma, cp.async 3-stage, ---------
//                      fused atomic-free logit epilogue, 2 CTAs/SM)
#define GBM 128
#define GBN 128
#define GBK 32
#define NK_IT (IN_DIM / GBK)      // 8
#define A_LD 36
#define B_LD 136
#define A_STG_B (GBM * A_LD * 4)
#define B_STG_B (GBK * B_LD * 4)
#define B_BASE_B (3 * A_STG_B)
#define GEMM_SMEM (3 * (A_STG_B + B_STG_B))  // 107520

__global__ __launch_bounds__(256, 2) void gemm_tf32_kernel(
    const float* __restrict__ X, const float* __restrict__ Wm,
    const float* __restrict__ att_src, const float* __restrict__ att_dst)
{
    extern __shared__ char smem_raw[];
    float* Asf = reinterpret_cast<float*>(smem_raw);
    float* Bsf = reinterpret_cast<float*>(smem_raw + B_BASE_B);
    const uint32_t sbase = (uint32_t)__cvta_generic_to_shared(smem_raw);

    const int tid  = threadIdx.x;
    const int wid  = tid >> 5;
    const int lane = tid & 31;
    const int m0 = blockIdx.x * GBM;
    const int n0 = blockIdx.y * GBN;
    const int wm = (wid & 1) * 64;
    const int wn = (wid >> 1) * 32;
    const int gID = lane >> 2;
    const int tig = lane & 3;

#define ISSUE_STAGE(K0, STG) do {                                              \
        _Pragma("unroll")                                                      \
        for (int l = 0; l < 4; l++) {                                          \
            int idx = tid + l * 256;                                           \
            int row = idx >> 3, c4 = idx & 7;                                  \
            int gm = m0 + row;                                                 \
            int sz = (gm < N_NODES) ? 16 : 0;                                  \
            if (gm >= N_NODES) gm = N_NODES - 1;                               \
            uint32_t dst = sbase + (STG) * A_STG_B + row * (A_LD * 4) + c4 * 16;\
            const char* src = (const char*)X + (size_t)gm * (IN_DIM * 4)       \
                              + (K0) * 4 + c4 * 16;                            \
            asm volatile("cp.async.cg.shared.global [%0], [%1], 16, %2;"       \
                         :: "r"(dst), "l"(src), "r"(sz));                      \
        }                                                                      \
        _Pragma("unroll")                                                      \
        for (int l = 0; l < 4; l++) {                                          \
            int idx = tid + l * 256;                                           \
            int kr = idx >> 5, c4 = idx & 31;                                  \
            uint32_t dst = sbase + B_BASE_B + (STG) * B_STG_B                  \
                           + kr * (B_LD * 4) + c4 * 16;                        \
            const char* src = (const char*)Wm                                  \
                + ((size_t)((K0) + kr) * OUT_DIM + n0) * 4 + c4 * 16;          \
            asm volatile("cp.async.cg.shared.global [%0], [%1], 16;"           \
                         :: "r"(dst), "l"(src));                               \
        }                                                                      \
        asm volatile("cp.async.commit_group;" ::: "memory");                   \
    } while (0)

    float c[4][4][4];
#pragma unroll
    for (int i = 0; i < 4; i++)
#pragma unroll
        for (int j = 0; j < 4; j++)
#pragma unroll
            for (int r = 0; r < 4; r++) c[i][j][r] = 0.f;

    ISSUE_STAGE(0, 0);
    ISSUE_STAGE(GBK, 1);

    for (int it = 0; it < NK_IT; it++) {
        if (it == NK_IT - 1) asm volatile("cp.async.wait_group 0;" ::: "memory");
        else                 asm volatile("cp.async.wait_group 1;" ::: "memory");
        __syncthreads();

        const int stg = it % 3;
        const float* Af = Asf + stg * (GBM * A_LD);
        const float* Bf = Bsf + stg * (GBK * B_LD);

#pragma unroll
        for (int ks = 0; ks < 4; ks++) {
            const int kb = ks * 8;
            uint32_t a[4][4], b[4][2];
#pragma unroll
            for (int mt = 0; mt < 4; mt++) {
                int rb = wm + mt * 16;
                a[mt][0] = f2tf32(Af[(rb + gID    ) * A_LD + kb + tig    ]);
                a[mt][1] = f2tf32(Af[(rb + gID + 8) * A_LD + kb + tig    ]);
                a[mt][2] = f2tf32(Af[(rb + gID    ) * A_LD + kb + tig + 4]);
                a[mt][3] = f2tf32(Af[(rb + gID + 8) * A_LD + kb + tig + 4]);
            }
#pragma unroll
            for (int nt = 0; nt < 4; nt++) {
                int col = wn + nt * 8 + gID;
                b[nt][0] = f2tf32(Bf[(kb + tig    ) * B_LD + col]);
                b[nt][1] = f2tf32(Bf[(kb + tig + 4) * B_LD + col]);
            }
#pragma unroll
            for (int mt = 0; mt < 4; mt++)
#pragma unroll
                for (int nt = 0; nt < 4; nt++) {
                    asm volatile(
                        "mma.sync.aligned.m16n8k8.row.col.f32.tf32.tf32.f32 "
                        "{%0,%1,%2,%3}, {%4,%5,%6,%7}, {%8,%9}, {%0,%1,%2,%3};"
                        : "+f"(c[mt][nt][0]), "+f"(c[mt][nt][1]),
                          "+f"(c[mt][nt][2]), "+f"(c[mt][nt][3])
                        : "r"(a[mt][0]), "r"(a[mt][1]), "r"(a[mt][2]), "r"(a[mt][3]),
                          "r"(b[nt][0]), "r"(b[nt][1]));
                }
        }

        if (it + 2 < NK_IT) {
            ISSUE_STAGE((it + 2) * GBK, (it + 2) % 3);
        }
    }
#undef ISSUE_STAGE

    // ---- epilogue 1: fp16 xp stores ----
#pragma unroll
    for (int mt = 0; mt < 4; mt++) {
        int r0 = m0 + wm + mt * 16 + gID;
#pragma unroll
        for (int nt = 0; nt < 4; nt++) {
            int col = n0 + wn + nt * 8 + 2 * tig;
            if (r0 < N_NODES) {
                __half2 v01 = __floats2half2_rn(c[mt][nt][0], c[mt][nt][1]);
                *reinterpret_cast<__half2*>(g_xph + (size_t)r0 * OUT_DIM + col) = v01;
            }
            if (r0 + 8 < N_NODES) {
                __half2 v23 = __floats2half2_rn(c[mt][nt][2], c[mt][nt][3]);
                *reinterpret_cast<__half2*>(g_xph + (size_t)(r0 + 8) * OUT_DIM + col) = v23;
            }
        }
    }

    // ---- epilogue 2: attention logits, atomic-free -------------------------
    float psrc0[4], psrc1[4], pdst0[4], pdst1[4];
#pragma unroll
    for (int mt = 0; mt < 4; mt++) {
        psrc0[mt] = psrc1[mt] = pdst0[mt] = pdst1[mt] = 0.f;
#pragma unroll
        for (int nt = 0; nt < 4; nt++) {
            int col = n0 + wn + nt * 8 + 2 * tig;
            float as0 = att_src[col], as1 = att_src[col + 1];
            float ad0 = att_dst[col], ad1 = att_dst[col + 1];
            psrc0[mt] += c[mt][nt][0] * as0 + c[mt][nt][1] * as1;
            psrc1[mt] += c[mt][nt][2] * as0 + c[mt][nt][3] * as1;
            pdst0[mt] += c[mt][nt][0] * ad0 + c[mt][nt][1] * ad1;
            pdst1[mt] += c[mt][nt][2] * ad0 + c[mt][nt][3] * ad1;
        }
    }
#pragma unroll
    for (int off = 1; off <= 2; off <<= 1) {
#pragma unroll
        for (int mt = 0; mt < 4; mt++) {
            psrc0[mt] += __shfl_xor_sync(0xffffffffu, psrc0[mt], off);
            psrc1[mt] += __shfl_xor_sync(0xffffffffu, psrc1[mt], off);
            pdst0[mt] += __shfl_xor_sync(0xffffffffu, pdst0[mt], off);
            pdst1[mt] += __shfl_xor_sync(0xffffffffu, pdst1[mt], off);
        }
    }
    float* red = reinterpret_cast<float*>(smem_raw);   // reuse pipeline smem
    __syncthreads();
    if (tig == 0) {
#pragma unroll
        for (int mt = 0; mt < 4; mt++) {
            int base = wid * 128 + mt * 32 + gID;
            red[base +  0] = psrc0[mt];
            red[base +  8] = psrc1[mt];
            red[base + 16] = pdst0[mt];
            red[base + 24] = pdst1[mt];
        }
    }
    __syncthreads();
    if ((((wid >> 1) & 1) == 0) && tig == 0) {
        int pw = wid + 2;                       // partner warp (wn + 32)
        int h = (n0 + wn) >> 6;                 // global head 0..3
#pragma unroll
        for (int mt = 0; mt < 4; mt++) {
            int pb = pw * 128 + mt * 32 + gID;
            float s0 = psrc0[mt] + red[pb +  0];
            float s1 = psrc1[mt] + red[pb +  8];
            float d0 = pdst0[mt] + red[pb + 16];
            float d1 = pdst1[mt] + red[pb + 24];
            int r0 = m0 + wm + mt * 16 + gID;
            if (r0 < N_NODES) {
                g_asrc[r0 * 4 + h] = s0;
                g_adst[r0 * 4 + h] = d0;
            }
            if (r0 + 8 < N_NODES) {
                g_asrc[(r0 + 8) * 4 + h] = s1;
                g_adst[(r0 + 8) * 4 + h] = d1;
            }
        }
    }
}

// ---------------- K3a: in-degree histogram ---------------------------------
__global__ __launch_bounds__(256) void hist_kernel(const void* __restrict__ ei)
{
    int i = blockIdx.x * blockDim.x + threadIdx.x;
    if (i >= E_TOT) return;
    int s, d;
    if (i < N_EDGES) load_edge(ei, i, s, d);
    else             d = i - N_EDGES;
    atomicAdd(&g_deg[d], 1);
}

// ---------------- K3b: fused exclusive scan (last-block-done pattern) ------
__global__ __launch_bounds__(256) void scan_fused_kernel()
{
    __shared__ int sm[256];
    __shared__ bool isLast;
    int tid = threadIdx.x;
    int i = blockIdx.x * 256 + tid;
    int v = (i < N_NODES) ? g_deg[i] : 0;
    sm[tid] = v;
    __syncthreads();
#pragma unroll
    for (int off = 1; off < 256; off <<= 1) {
        int t = (tid >= off) ? sm[tid - off] : 0;
        __syncthreads();
        sm[tid] += t;
        __syncthreads();
    }
    int incl = sm[tid];
    if (i < N_NODES) {
        int excl = incl - v;
        g_off[i] = excl;
        g_cur[i] = excl;
    }
    if (tid == 255) g_bsum[blockIdx.x] = incl;

    __threadfence();
    if (tid == 0) {
        int ticket = atomicAdd(&g_scan_ctr, 1);
        isLast = (ticket == gridDim.x - 1);
    }
    __syncthreads();
    if (isLast) {
        int bv = (tid < NBLK_SCAN) ? g_bsum[tid] : 0;
        sm[tid] = bv;
        __syncthreads();
#pragma unroll
        for (int off = 1; off < 256; off <<= 1) {
            int t = (tid >= off) ? sm[tid - off] : 0;
            __syncthreads();
            sm[tid] += t;
            __syncthreads();
        }
        if (tid < NBLK_SCAN) g_boff[tid] = sm[tid] - bv;
    }
}

// ---------------- K3c: scatter edges into CSR order (index only) -----------
__global__ __launch_bounds__(256) void scatter_kernel(const void* __restrict__ ei)
{
    int i = blockIdx.x * blockDim.x + threadIdx.x;
    if (i >= E_TOT) return;
    int s, d;
    if (i < N_EDGES) load_edge(ei, i, s, d);
    else             s = d = i - N_EDGES;   // self-loop

    int pos = atomicAdd(&g_cur[d], 1) + g_boff[d >> 8];
    g_csr_src[pos] = s;
}

// ---------------- K4: CSR aggregate with inline softmax + ReLU -------------
// Simple loop, 1 warp/node — the empirically fastest form (R14).
__global__ __launch_bounds__(256) void aggregate_csr_kernel(float* __restrict__ out)
{
    int d = (blockIdx.x * blockDim.x + threadIdx.x) >> 5;
    if (d >= N_NODES) return;
    int lane = threadIdx.x & 31;
    int h = lane >> 3;
    int boff = g_boff[d >> 8];
    int beg = g_off[d] + boff;
    int end = g_cur[d] + boff;
    float adh = __ldg(g_adst + d * 4 + h);   // invariant over the row

    float a0 = 0.f, a1 = 0.f, a2 = 0.f, a3 = 0.f;
    float a4 = 0.f, a5 = 0.f, a6 = 0.f, a7 = 0.f;
    float denom = 0.f;

    for (int j = beg; j < end; j++) {
        int   s  = __ldg(g_csr_src + j);
        float e  = __ldg(g_asrc + s * 4 + h) + adh;
        e = (e > 0.f) ? e : NEG_SLOPE * e;
        float ee = __expf(e);
        denom += ee;
        uint4 u = __ldg(reinterpret_cast<const uint4*>(
            g_xph + (size_t)s * OUT_DIM + lane * 8));
        const __half2* hp = reinterpret_cast<const __half2*>(&u);
        float2 f0 = __half22float2(hp[0]);
        float2 f1 = __half22float2(hp[1]);
        float2 f2 = __half22float2(hp[2]);
        float2 f3 = __half22float2(hp[3]);
        a0 += ee * f0.x; a1 += ee * f0.y;
        a2 += ee * f1.x; a3 += ee * f1.y;
        a4 += ee * f2.x; a5 += ee * f2.y;
        a6 += ee * f3.x; a7 += ee * f3.y;
    }

    float inv = 1.f / denom;
    float4 o0 = make_float4(fmaxf(a0 * inv, 0.f), fmaxf(a1 * inv, 0.f),
                            fmaxf(a2 * inv, 0.f), fmaxf(a3 * inv, 0.f));
    float4 o1 = make_float4(fmaxf(a4 * inv, 0.f), fmaxf(a5 * inv, 0.f),
                            fmaxf(a6 * inv, 0.f), fmaxf(a7 * inv, 0.f));
    float4* op = reinterpret_cast<float4*>(out + (size_t)d * OUT_DIM + lane * 8);
    __stcs(op, o0);
    __stcs(op + 1, o1);
}

// ---------------- launch ----------------------------------------------------
extern "C" void kernel_launch(void* const* d_in, const int* in_sizes, int n_in,
                              void* d_out, int out_size)
{
    const float* x       = (const float*)d_in[0];
    const void*  ei      = d_in[1];
    const float* Wm      = (const float*)d_in[2];
    const float* att_src = (const float*)d_in[3];
    const float* att_dst = (const float*)d_in[4];
    float*       out     = (float*)d_out;

    static cudaStream_t s1 = nullptr;
    static cudaEvent_t evFork = nullptr, evJoin = nullptr;
    if (!s1) {
        cudaStreamCreateWithFlags(&s1, cudaStreamNonBlocking);
        cudaEventCreateWithFlags(&evFork, cudaEventDisableTiming);
        cudaEventCreateWithFlags(&evJoin, cudaEventDisableTiming);
        cudaFuncSetAttribute(gemm_tf32_kernel,
                             cudaFuncAttributeMaxDynamicSharedMemorySize, GEMM_SMEM);
    }

    cudaEventRecord(evFork, 0);
    cudaStreamWaitEvent(s1, evFork, 0);

    // branch B (side stream): deg-zero+detect -> hist -> scan -> scatter
    zero_deg_kernel<<<NBLK_SCAN, 256, 0, s1>>>((const int*)ei);
    hist_kernel<<<(E_TOT + 255) / 256, 256, 0, s1>>>(ei);
    scan_fused_kernel<<<NBLK_SCAN, 256, 0, s1>>>();
    scatter_kernel<<<(E_TOT + 255) / 256, 256, 0, s1>>>(ei);
    cudaEventRecord(evJoin, s1);

    // branch A (main stream): GEMM + atomic-free logit epilogue
    dim3 ggrid((N_NODES + GBM - 1) / GBM, OUT_DIM / GBN);
    gemm_tf32_kernel<<<ggrid, 256, GEMM_SMEM>>>(x, Wm, att_src, att_dst);

    // join: aggregate needs logits+xp (A) and CSR (B)
    cudaStreamWaitEvent(0, evJoin, 0);
    aggregate_csr_kernel<<<((size_t)N_NODES * 32 + 255) / 256, 256>>>(out);
}